// round 8
// baseline (speedup 1.0000x reference)
#include <cuda_runtime.h>
#include <cstdint>
#include <math.h>

// ---------------- problem constants ----------------
#define BDIM 256
#define DIN 2048
#define HID 2048
#define DCTX 1024
#define NSEG 10
#define NR (HID * NSEG) /* 20480 */
#define OUTD 100
#define KWIN 102

#define DW 128    // ELL row width for dendrite rows (mean nz 51.2)
#define FW 192    // ELL width for FF rows (mean nz 102.4)

typedef unsigned long long u64;

// ---------------- scratch (no allocations allowed) ----------------
__device__ float g_ctxT[DCTX * BDIM];       // 1 MB  context transposed [c][b]
__device__ float g_xT[DIN * BDIM];          // 2 MB  x transposed [c][b]
__device__ float g_hT[HID * BDIM];          // 2 MB  layer-1 winners transposed [c][b]
__device__ float g_y[BDIM * HID];           // 2 MB  gated ff activation ROW-MAJOR [b][n]
__device__ float g_gT1[HID * BDIM];         // 2 MB  dendrite gate layer 1 [u][b]
__device__ float g_gT2[HID * BDIM];         // 2 MB  dendrite gate layer 2 [u][b]
__device__ float g_h2[BDIM * HID];          // 2 MB  layer-2 winners, row-major
__device__ u64  g_ellD1[(size_t)NR * DW];   // 21 MB ELL (dendrite L1)
__device__ u64  g_ellD2[(size_t)NR * DW];   // 21 MB ELL (dendrite L2)
__device__ int  g_cntD1[NR];
__device__ int  g_cntD2[NR];
__device__ u64  g_ellF1[(size_t)HID * FW];  // 3 MB  ELL (ff L1)
__device__ u64  g_ellF2[(size_t)HID * FW];  // 3 MB  ELL (ff L2)
__device__ int  g_cntF1[HID];
__device__ int  g_cntF2[HID];

// =====================================================================
// warp-per-row ELL compaction, depth-2 register prefetch (4 loads in
// flight). entry = (f32 bits << 32) | (col * mult), ascending cols.
// =====================================================================
__device__ __forceinline__
void build_row(const float* __restrict__ W, const float* __restrict__ M,
               u64* __restrict__ ell, int* __restrict__ cnt,
               int K, int width, int mult, int row, int lane) {
    const float4* wr = (const float4*)(W + (size_t)row * K);
    const float4* mr = (const float4*)(M + (size_t)row * K);
    u64* er = ell + (size_t)row * width;
    const int chunks = K >> 7;  // 128 floats per chunk (float4 per lane)
    int base = 0;
    float4 w0 = wr[lane],      m0 = mr[lane];
    float4 w1 = wr[32 + lane], m1 = mr[32 + lane];  // chunks >= 2 always here
    for (int c = 0; c < chunks; ++c) {
        float4 wn, mn;
        if (c + 2 < chunks) {
            wn = wr[(c + 2) * 32 + lane];
            mn = mr[(c + 2) * 32 + lane];
        }
        const int cn = (m0.x != 0.f) + (m0.y != 0.f) + (m0.z != 0.f) + (m0.w != 0.f);
        int inc = cn;
#pragma unroll
        for (int o = 1; o < 32; o <<= 1) {
            const int t = __shfl_up_sync(0xffffffffu, inc, o);
            if (lane >= o) inc += t;
        }
        const int tot = __shfl_sync(0xffffffffu, inc, 31);
        int p = base + inc - cn;  // exclusive position
        const int col0 = c * 128 + lane * 4;
        if (m0.x != 0.f && p < width) er[p++] = ((u64)__float_as_uint(w0.x) << 32) | (unsigned)((col0 + 0) * mult);
        if (m0.y != 0.f && p < width) er[p++] = ((u64)__float_as_uint(w0.y) << 32) | (unsigned)((col0 + 1) * mult);
        if (m0.z != 0.f && p < width) er[p++] = ((u64)__float_as_uint(w0.z) << 32) | (unsigned)((col0 + 2) * mult);
        if (m0.w != 0.f && p < width) er[p++] = ((u64)__float_as_uint(w0.w) << 32) | (unsigned)((col0 + 3) * mult);
        base += tot;
        w0 = w1; m0 = m1;
        w1 = wn; m1 = mn;
    }
    if (lane == 0) cnt[row] = base < width ? base : width;
}

// =====================================================================
// K1: fused prep — all four ELL builds + both transposes in one launch.
// Block ranges:
//   [0,2560)      build dendrite L1   (8 rows/block, /2560 %2560 decode)
//   [2560,5120)   build dendrite L2
//   [5120,5376)   build FF L1
//   [5376,5632)   build FF L2
//   [5632,5888)   transpose ctx
//   [5888,6400)   transpose x
// =====================================================================
__global__ __launch_bounds__(256)
void prep_k(const float* __restrict__ segW1, const float* __restrict__ maskS1,
            const float* __restrict__ segW2, const float* __restrict__ maskS2,
            const float* __restrict__ W1, const float* __restrict__ maskW1,
            const float* __restrict__ W2, const float* __restrict__ maskW2,
            const float* __restrict__ ctx, const float* __restrict__ x) {
    const int bid = blockIdx.x;
    const int tid = threadIdx.x;
    const int lane = tid & 31;
    const int wid = tid >> 5;

    if (bid < 5120) {  // dendrite builds
        const int part = bid / 2560;                 // 0 or 1
        const int row = (bid % 2560) * 8 + wid;      // 0..20479
        if (part == 0) build_row(segW1, maskS1, g_ellD1, g_cntD1, DCTX, DW, 128, row, lane);
        else           build_row(segW2, maskS2, g_ellD2, g_cntD2, DCTX, DW, 128, row, lane);
        return;
    }
    if (bid < 5632) {  // FF builds
        const int part = (bid - 5120) >> 8;          // 0 or 1 (256 blocks each)
        const int row = ((bid - 5120) & 255) * 8 + wid;
        if (part == 0) build_row(W1, maskW1, g_ellF1, g_cntF1, DIN, FW, 1024, row, lane);
        else           build_row(W2, maskW2, g_ellF2, g_cntF2, HID, FW, 1024, row, lane);
        return;
    }
    // transposes: in[R=256][C] -> out[C][256]
    __shared__ float t[32][33];
    const float* in;
    float* outp;
    int C, lb;
    if (bid < 5888) { in = ctx; outp = g_ctxT; C = DCTX; lb = bid - 5632; }
    else            { in = x;   outp = g_xT;   C = DIN;  lb = bid - 5888; }
    const int nbx = C >> 5;
    const int c0 = (lb % nbx) * 32;
    const int r0 = (lb / nbx) * 32;
    const int xx = tid & 31, yy = tid >> 5;
#pragma unroll
    for (int i = 0; i < 32; i += 8)
        t[yy + i][xx] = in[(size_t)(r0 + yy + i) * C + c0 + xx];
    __syncthreads();
#pragma unroll
    for (int i = 0; i < 32; i += 8)
        outp[(size_t)(c0 + yy + i) * BDIM + r0 + xx] = t[xx][yy + i];
}

// =====================================================================
// K2: fused dendrite spMM + gate for BOTH layers.
// 1024 threads (32 warps), smem = 32-batch ctx tile (128 KB).
// Entry loop unrolled x8 with dual accumulator chains -> 8 LDG.64 in
// flight per warp. grid 256: [layer(2)][by(8)][bx(16)].
// =====================================================================
__global__ __launch_bounds__(1024, 1)
void dspmm_gate2(const float* __restrict__ ctxT) {
    extern __shared__ float s[];  // DCTX * 32 floats = 128 KB
    const int id = blockIdx.x;
    const int layer = id >> 7;
    const int bx = id & 15;
    const int by = (id & 127) >> 4;
    const u64* __restrict__ ell = layer ? g_ellD2 : g_ellD1;
    const int* __restrict__ cnt = layer ? g_cntD2 : g_cntD1;
    float* __restrict__ gT = layer ? g_gT2 : g_gT1;

    const int b0 = by * 32;
    const int tid = threadIdx.x;
    for (int i = tid; i < DCTX * 8; i += 1024) {
        const int c = i >> 3, q = (i & 7) * 4;
        *(float4*)&s[c * 32 + q] =
            *(const float4*)&ctxT[(size_t)c * 256 + b0 + q];
    }
    __syncthreads();
    const int wid = tid >> 5, lane = tid & 31;
    const char* sb = (const char*)s + lane * 4;

#pragma unroll
    for (int i = 0; i < 4; ++i) {
        const int u = bx * 128 + wid * 4 + i;
        const int r0 = u * NSEG;
        int cn = (lane < NSEG) ? cnt[r0 + lane] : 0;
        if (cn > DW) cn = DW;
        float accs[NSEG];
#pragma unroll
        for (int sg = 0; sg < NSEG; ++sg) {
            const int n = __shfl_sync(0xffffffffu, cn, sg);
            const u64* e = ell + (size_t)(r0 + sg) * DW;
            float a0 = 0.f, a1 = 0.f;
            int j = 0;
            for (; j + 8 <= n; j += 8) {
                const u64 e0 = e[j],     e1 = e[j + 1], e2 = e[j + 2], e3 = e[j + 3];
                const u64 e4 = e[j + 4], e5 = e[j + 5], e6 = e[j + 6], e7 = e[j + 7];
                a0 += __uint_as_float((unsigned)(e0 >> 32)) * *(const float*)(sb + (unsigned)e0);
                a1 += __uint_as_float((unsigned)(e1 >> 32)) * *(const float*)(sb + (unsigned)e1);
                a0 += __uint_as_float((unsigned)(e2 >> 32)) * *(const float*)(sb + (unsigned)e2);
                a1 += __uint_as_float((unsigned)(e3 >> 32)) * *(const float*)(sb + (unsigned)e3);
                a0 += __uint_as_float((unsigned)(e4 >> 32)) * *(const float*)(sb + (unsigned)e4);
                a1 += __uint_as_float((unsigned)(e5 >> 32)) * *(const float*)(sb + (unsigned)e5);
                a0 += __uint_as_float((unsigned)(e6 >> 32)) * *(const float*)(sb + (unsigned)e6);
                a1 += __uint_as_float((unsigned)(e7 >> 32)) * *(const float*)(sb + (unsigned)e7);
            }
            for (; j < n; ++j) {
                const u64 e0 = e[j];
                a0 += __uint_as_float((unsigned)(e0 >> 32)) * *(const float*)(sb + (unsigned)e0);
            }
            accs[sg] = a0 + a1;
        }
        // first-occurrence abs-argmax (strict >) + sigmoid
        float best = accs[0];
        float ba = fabsf(best);
#pragma unroll
        for (int sg = 1; sg < NSEG; ++sg) {
            const float v = accs[sg];
            const float a = fabsf(v);
            if (a > ba) { ba = a; best = v; }
        }
        gT[(size_t)u * 256 + b0 + lane] = 1.0f / (1.0f + __expf(-best));
    }
}

// =====================================================================
// FF spMM, 8 rows/block, gate fused, ROW-MAJOR output:
// y[b][r] = (bias[r] + sum w*xT[c][b]) * gT[r][b]
// Each thread owns batch b=tid, writes its 8 contiguous floats (32 B).
// =====================================================================
__global__ __launch_bounds__(256)
void fspmm8(const float* __restrict__ xT, const u64* __restrict__ ell,
            const int* __restrict__ cnt, const float* __restrict__ bias,
            const float* __restrict__ gT, float* __restrict__ y) {
    __shared__ u64 fe[8][FW];
    __shared__ int s_n[8];
    __shared__ float s_b[8];
    const int r0 = blockIdx.x * 8;
    const int tid = threadIdx.x;
    if (tid < 8) {
        int n = cnt[r0 + tid];
        s_n[tid] = n < FW ? n : FW;
        s_b[tid] = bias[r0 + tid];
    }
    __syncthreads();
#pragma unroll
    for (int q = 0; q < 8; ++q) {
        const int n = s_n[q];
        for (int j = tid; j < n; j += 256) fe[q][j] = ell[(size_t)(r0 + q) * FW + j];
    }
    __syncthreads();
    const char* xb = (const char*)xT + tid * 4;
    float val[8];
#pragma unroll
    for (int q = 0; q < 8; ++q) {
        const int n = s_n[q];
        const u64* e = fe[q];
        float a0 = 0.f, a1 = 0.f;
        int j = 0;
        for (; j + 8 <= n; j += 8) {
            const u64 e0 = e[j],     e1 = e[j + 1], e2 = e[j + 2], e3 = e[j + 3];
            const u64 e4 = e[j + 4], e5 = e[j + 5], e6 = e[j + 6], e7 = e[j + 7];
            a0 += __uint_as_float((unsigned)(e0 >> 32)) * *(const float*)(xb + (unsigned)e0);
            a1 += __uint_as_float((unsigned)(e1 >> 32)) * *(const float*)(xb + (unsigned)e1);
            a0 += __uint_as_float((unsigned)(e2 >> 32)) * *(const float*)(xb + (unsigned)e2);
            a1 += __uint_as_float((unsigned)(e3 >> 32)) * *(const float*)(xb + (unsigned)e3);
            a0 += __uint_as_float((unsigned)(e4 >> 32)) * *(const float*)(xb + (unsigned)e4);
            a1 += __uint_as_float((unsigned)(e5 >> 32)) * *(const float*)(xb + (unsigned)e5);
            a0 += __uint_as_float((unsigned)(e6 >> 32)) * *(const float*)(xb + (unsigned)e6);
            a1 += __uint_as_float((unsigned)(e7 >> 32)) * *(const float*)(xb + (unsigned)e7);
        }
        for (; j < n; ++j) {
            const u64 e0 = e[j];
            a0 += __uint_as_float((unsigned)(e0 >> 32)) * *(const float*)(xb + (unsigned)e0);
        }
        val[q] = (a0 + a1 + s_b[q]) * gT[(size_t)(r0 + q) * 256 + tid];
    }
    float4 v0 = make_float4(val[0], val[1], val[2], val[3]);
    float4 v1 = make_float4(val[4], val[5], val[6], val[7]);
    float* yr = y + (size_t)tid * HID + r0;
    *(float4*)yr = v0;
    *(float4*)(yr + 4) = v1;
}

// =====================================================================
// k-winners: exact top-KWIN per sample (y is row-major, coalesced).
// 4-pass radix select, single-warp shfl suffix scan for bin selection.
// mode 0 -> transposed hT[i][b]; mode 1 -> row-major h2[b][i].
// =====================================================================
__global__ __launch_bounds__(256)
void kwinners_k(const float* __restrict__ y, float* __restrict__ outT,
                float* __restrict__ outN, int mode) {
    __shared__ unsigned keys[HID];
    __shared__ int hist[256];
    __shared__ int s_digit;
    __shared__ int s_need;
    const int b = blockIdx.x, tid = threadIdx.x;
    const float* row = y + (size_t)b * HID;
    for (int i = tid; i < HID; i += 256) {
        unsigned u = __float_as_uint(row[i]);
        u = (u & 0x80000000u) ? ~u : (u | 0x80000000u);  // monotonic ascending
        keys[i] = u;
    }
    if (tid == 0) s_need = KWIN;
    __syncthreads();

    unsigned prefix = 0, pmask = 0;
    for (int pass = 0; pass < 4; ++pass) {
        const int shift = 24 - 8 * pass;
        hist[tid] = 0;
        __syncthreads();
        for (int i = tid; i < HID; i += 256) {
            const unsigned u = keys[i];
            if ((u & pmask) == prefix) atomicAdd(&hist[(u >> shift) & 255], 1);
        }
        __syncthreads();
        if (tid < 32) {
            const int need = s_need;
            const int base = tid * 8;
            int gs = 0;
#pragma unroll
            for (int k = 0; k < 8; ++k) gs += hist[base + k];
            int S = gs;  // inclusive suffix sum across lanes
#pragma unroll
            for (int o = 1; o < 32; o <<= 1) {
                const int t = __shfl_down_sync(0xffffffffu, S, o);
                if (tid + o < 32) S += t;
            }
            int Snext = __shfl_down_sync(0xffffffffu, S, 1);
            if (tid == 31) Snext = 0;
            if (S >= need && Snext < need) {  // unique crossing lane
                int c = Snext;
#pragma unroll
                for (int k = 7; k >= 0; --k) {
                    const int hb = hist[base + k];
                    if (c + hb >= need) { s_digit = base + k; s_need = need - c; break; }
                    c += hb;
                }
            }
        }
        __syncthreads();
        prefix |= ((unsigned)s_digit) << shift;
        pmask |= 0xFFu << shift;
    }
    const unsigned thr = prefix;  // key of the KWIN-th largest
    for (int i = tid; i < HID; i += 256) {
        const unsigned u = keys[i];
        float val = 0.f;
        if (u >= thr) {
            const unsigned ob = (u & 0x80000000u) ? (u & 0x7FFFFFFFu) : ~u;
            val = __uint_as_float(ob);
        }
        if (mode == 0) outT[(size_t)i * 256 + b] = val;
        else           outN[(size_t)b * HID + i] = val;
    }
}

// =====================================================================
// EiDense head: out[b,o] = h.Wex[o] - (h.Wix)*Wei[o] + b_out[o]
// =====================================================================
__global__ __launch_bounds__(256)
void head_kernel(const float* __restrict__ h, const float* __restrict__ Wex,
                 const float* __restrict__ Wix, const float* __restrict__ Wei,
                 const float* __restrict__ bo, float* __restrict__ out) {
    __shared__ alignas(16) float sh[4][HID];
    __shared__ float st[4];
    const int b0 = blockIdx.x * 4;
    const int tid = threadIdx.x;
    for (int i = tid; i < 4 * HID; i += 256)
        (&sh[0][0])[i] = h[(size_t)b0 * HID + i];
    __syncthreads();
    const int wid = tid >> 5;
    const int lane = tid & 31;
    if (wid < 4) {
        float p = 0.f;
        for (int u = lane; u < HID; u += 32) p += sh[wid][u] * Wix[u];
#pragma unroll
        for (int o = 16; o; o >>= 1) p += __shfl_xor_sync(0xffffffffu, p, o);
        if (lane == 0) st[wid] = p;
    }
    __syncthreads();
    for (int o = wid; o < OUTD; o += 8) {
        float a0 = 0.f, a1 = 0.f, a2 = 0.f, a3 = 0.f;
        const float* wrow = Wex + (size_t)o * HID;
        for (int u = lane; u < HID; u += 32) {
            const float w = wrow[u];
            a0 += sh[0][u] * w;
            a1 += sh[1][u] * w;
            a2 += sh[2][u] * w;
            a3 += sh[3][u] * w;
        }
#pragma unroll
        for (int sft = 16; sft; sft >>= 1) {
            a0 += __shfl_xor_sync(0xffffffffu, a0, sft);
            a1 += __shfl_xor_sync(0xffffffffu, a1, sft);
            a2 += __shfl_xor_sync(0xffffffffu, a2, sft);
            a3 += __shfl_xor_sync(0xffffffffu, a3, sft);
        }
        if (lane == 0) {
            const float we = Wei[o];
            const float bb = bo[o];
            out[(size_t)(b0 + 0) * OUTD + o] = a0 - st[0] * we + bb;
            out[(size_t)(b0 + 1) * OUTD + o] = a1 - st[1] * we + bb;
            out[(size_t)(b0 + 2) * OUTD + o] = a2 - st[2] * we + bb;
            out[(size_t)(b0 + 3) * OUTD + o] = a3 - st[3] * we + bb;
        }
    }
}

// =====================================================================
// launch
// =====================================================================
extern "C" void kernel_launch(void* const* d_in, const int* in_sizes, int n_in,
                              void* d_out, int out_size) {
    const float* x      = (const float*)d_in[0];
    const float* ctx    = (const float*)d_in[1];
    const float* W1     = (const float*)d_in[2];
    const float* b1     = (const float*)d_in[3];
    const float* segW1  = (const float*)d_in[4];
    const float* maskW1 = (const float*)d_in[5];
    const float* maskS1 = (const float*)d_in[6];
    const float* W2     = (const float*)d_in[7];
    const float* b2     = (const float*)d_in[8];
    const float* segW2  = (const float*)d_in[9];
    const float* maskW2 = (const float*)d_in[10];
    const float* maskS2 = (const float*)d_in[11];
    const float* Wex    = (const float*)d_in[12];
    const float* Wix    = (const float*)d_in[13];
    const float* Wei    = (const float*)d_in[14];
    const float* bo     = (const float*)d_in[15];
    float* out = (float*)d_out;

    float *ctxT, *xT, *hT, *y, *gT1, *gT2, *h2;
    u64 *ellF1, *ellF2;
    int *cntF1, *cntF2;
    cudaGetSymbolAddress((void**)&ctxT,  g_ctxT);
    cudaGetSymbolAddress((void**)&xT,    g_xT);
    cudaGetSymbolAddress((void**)&hT,    g_hT);
    cudaGetSymbolAddress((void**)&y,     g_y);
    cudaGetSymbolAddress((void**)&gT1,   g_gT1);
    cudaGetSymbolAddress((void**)&gT2,   g_gT2);
    cudaGetSymbolAddress((void**)&h2,    g_h2);
    cudaGetSymbolAddress((void**)&ellF1, g_ellF1);
    cudaGetSymbolAddress((void**)&ellF2, g_ellF2);
    cudaGetSymbolAddress((void**)&cntF1, g_cntF1);
    cudaGetSymbolAddress((void**)&cntF2, g_cntF2);

    const int dsmem = DCTX * 32 * 4;  // 128 KB
    cudaFuncSetAttribute(dspmm_gate2, cudaFuncAttributeMaxDynamicSharedMemorySize, dsmem);

    // K1: all builds + transposes fused
    prep_k<<<6400, 256>>>(segW1, maskS1, segW2, maskS2,
                          W1, maskW1, W2, maskW2, ctx, x);
    // K2: both layers' dendrite gates (needs ctxT + ellD)
    dspmm_gate2<<<256, 1024, dsmem>>>(ctxT);
    // layer 1 FF + gate, row-major y
    fspmm8<<<HID / 8, 256>>>(xT, ellF1, cntF1, b1, gT1, y);
    // layer 1 k-winners -> hT (transposed, for fspmm2)
    kwinners_k<<<BDIM, 256>>>(y, hT, h2, 0);
    // layer 2 FF + gate
    fspmm8<<<HID / 8, 256>>>(hT, ellF2, cntF2, b2, gT2, y);
    // layer 2 k-winners -> h2 row-major
    kwinners_k<<<BDIM, 256>>>(y, hT, h2, 1);
    // EiDense head
    head_kernel<<<BDIM / 4, 256>>>(h2, Wex, Wix, Wei, bo, out);
}

// round 10
// speedup vs baseline: 1.1590x; 1.1590x over previous
#include <cuda_runtime.h>
#include <cstdint>
#include <math.h>

// ---------------- problem constants ----------------
#define BDIM 256
#define DIN 2048
#define HID 2048
#define DCTX 1024
#define NSEG 10
#define NR (HID * NSEG) /* 20480 */
#define OUTD 100
#define KWIN 102

#define DW 128    // ELL row width for dendrite rows (mean nz 51.2)
#define FW 192    // ELL width for FF rows (mean nz 102.4)

typedef unsigned long long u64;

// ---------------- scratch (no allocations allowed) ----------------
__device__ float g_ctxT[DCTX * BDIM];       // 1 MB  context transposed [c][b]
__device__ float g_xT[DIN * BDIM];          // 2 MB  x transposed [c][b]
__device__ float g_hT[HID * BDIM];          // 2 MB  layer-1 winners transposed [c][b]
__device__ float g_yT[HID * BDIM];          // 2 MB  gated ff activation [n][b]
__device__ float g_gT1[HID * BDIM];         // 2 MB  dendrite gate layer 1 [u][b]
__device__ float g_gT2[HID * BDIM];         // 2 MB  dendrite gate layer 2 [u][b]
__device__ float g_h2[BDIM * HID];          // 2 MB  layer-2 winners, row-major
__device__ u64  g_ellD1[(size_t)NR * DW];   // 21 MB ELL (dendrite L1)
__device__ u64  g_ellD2[(size_t)NR * DW];   // 21 MB ELL (dendrite L2)
__device__ int  g_cntD1[NR];
__device__ int  g_cntD2[NR];
__device__ u64  g_ellF1[(size_t)HID * FW];  // 3 MB  ELL (ff L1)
__device__ u64  g_ellF2[(size_t)HID * FW];  // 3 MB  ELL (ff L2)
__device__ int  g_cntF1[HID];
__device__ int  g_cntF2[HID];

// =====================================================================
// warp-per-row ELL compaction: float4 loads + shfl exclusive scan,
// depth-1 register prefetch (R6-proven).
// entry = (f32 weight bits << 32) | (col * mult), ascending cols.
// =====================================================================
__device__ __forceinline__
void build_row(const float* __restrict__ W, const float* __restrict__ M,
               u64* __restrict__ ell, int* __restrict__ cnt,
               int K, int width, int mult, int row, int lane) {
    const float4* wr = (const float4*)(W + (size_t)row * K);
    const float4* mr = (const float4*)(M + (size_t)row * K);
    u64* er = ell + (size_t)row * width;
    const int chunks = K >> 7;  // 128 floats per chunk (float4 per lane)
    int base = 0;
    float4 w = wr[lane];
    float4 m = mr[lane];
    for (int c = 0; c < chunks; ++c) {
        float4 wn, mn;
        if (c + 1 < chunks) {
            wn = wr[(c + 1) * 32 + lane];
            mn = mr[(c + 1) * 32 + lane];
        }
        const int cn = (m.x != 0.f) + (m.y != 0.f) + (m.z != 0.f) + (m.w != 0.f);
        int inc = cn;
#pragma unroll
        for (int o = 1; o < 32; o <<= 1) {
            const int t = __shfl_up_sync(0xffffffffu, inc, o);
            if (lane >= o) inc += t;
        }
        const int tot = __shfl_sync(0xffffffffu, inc, 31);
        int p = base + inc - cn;  // exclusive position
        const int col0 = c * 128 + lane * 4;
        if (m.x != 0.f && p < width) er[p++] = ((u64)__float_as_uint(w.x) << 32) | (unsigned)((col0 + 0) * mult);
        if (m.y != 0.f && p < width) er[p++] = ((u64)__float_as_uint(w.y) << 32) | (unsigned)((col0 + 1) * mult);
        if (m.z != 0.f && p < width) er[p++] = ((u64)__float_as_uint(w.z) << 32) | (unsigned)((col0 + 2) * mult);
        if (m.w != 0.f && p < width) er[p++] = ((u64)__float_as_uint(w.w) << 32) | (unsigned)((col0 + 3) * mult);
        base += tot;
        w = wn; m = mn;
    }
    if (lane == 0) cnt[row] = base < width ? base : width;
}

// =====================================================================
// K1: fused prep — all four ELL builds + both transposes in one launch.
// Block ranges:
//   [0,2560)      build dendrite L1   (8 rows/block, /2560 %2560 decode)
//   [2560,5120)   build dendrite L2
//   [5120,5376)   build FF L1
//   [5376,5632)   build FF L2
//   [5632,5888)   transpose ctx
//   [5888,6400)   transpose x
// =====================================================================
__global__ __launch_bounds__(256)
void prep_k(const float* __restrict__ segW1, const float* __restrict__ maskS1,
            const float* __restrict__ segW2, const float* __restrict__ maskS2,
            const float* __restrict__ W1, const float* __restrict__ maskW1,
            const float* __restrict__ W2, const float* __restrict__ maskW2,
            const float* __restrict__ ctx, const float* __restrict__ x) {
    const int bid = blockIdx.x;
    const int tid = threadIdx.x;
    const int lane = tid & 31;
    const int wid = tid >> 5;

    if (bid < 5120) {  // dendrite builds
        const int part = bid / 2560;                 // 0 or 1
        const int row = (bid % 2560) * 8 + wid;      // 0..20479
        if (part == 0) build_row(segW1, maskS1, g_ellD1, g_cntD1, DCTX, DW, 128, row, lane);
        else           build_row(segW2, maskS2, g_ellD2, g_cntD2, DCTX, DW, 128, row, lane);
        return;
    }
    if (bid < 5632) {  // FF builds
        const int part = (bid - 5120) >> 8;          // 0 or 1 (256 blocks each)
        const int row = ((bid - 5120) & 255) * 8 + wid;
        if (part == 0) build_row(W1, maskW1, g_ellF1, g_cntF1, DIN, FW, 1024, row, lane);
        else           build_row(W2, maskW2, g_ellF2, g_cntF2, HID, FW, 1024, row, lane);
        return;
    }
    // transposes: in[R=256][C] -> out[C][256]
    __shared__ float t[32][33];
    const float* in;
    float* outp;
    int C, lb;
    if (bid < 5888) { in = ctx; outp = g_ctxT; C = DCTX; lb = bid - 5632; }
    else            { in = x;   outp = g_xT;   C = DIN;  lb = bid - 5888; }
    const int nbx = C >> 5;
    const int c0 = (lb % nbx) * 32;
    const int r0 = (lb / nbx) * 32;
    const int xx = tid & 31, yy = tid >> 5;
#pragma unroll
    for (int i = 0; i < 32; i += 8)
        t[yy + i][xx] = in[(size_t)(r0 + yy + i) * C + c0 + xx];
    __syncthreads();
#pragma unroll
    for (int i = 0; i < 32; i += 8)
        outp[(size_t)(c0 + yy + i) * BDIM + r0 + xx] = t[xx][yy + i];
}

// =====================================================================
// K2: fused dendrite spMM + gate for BOTH layers (R6-proven config).
// 1024 threads (32 warps), smem = 32-batch ctx tile (128 KB).
// Unroll-4 inner loop — fits the 64-reg/thread budget at 1024 thr.
// grid 256: [layer(2)][by(8)][bx(16)].
// =====================================================================
__global__ __launch_bounds__(1024, 1)
void dspmm_gate2(const float* __restrict__ ctxT) {
    extern __shared__ float s[];  // DCTX * 32 floats = 128 KB
    const int id = blockIdx.x;
    const int layer = id >> 7;
    const int bx = id & 15;
    const int by = (id & 127) >> 4;
    const u64* __restrict__ ell = layer ? g_ellD2 : g_ellD1;
    const int* __restrict__ cnt = layer ? g_cntD2 : g_cntD1;
    float* __restrict__ gT = layer ? g_gT2 : g_gT1;

    const int b0 = by * 32;
    const int tid = threadIdx.x;
    for (int i = tid; i < DCTX * 8; i += 1024) {
        const int c = i >> 3, q = (i & 7) * 4;
        *(float4*)&s[c * 32 + q] =
            *(const float4*)&ctxT[(size_t)c * 256 + b0 + q];
    }
    __syncthreads();
    const int wid = tid >> 5, lane = tid & 31;
    const char* sb = (const char*)s + lane * 4;

#pragma unroll
    for (int i = 0; i < 4; ++i) {
        const int u = bx * 128 + wid * 4 + i;
        const int r0 = u * NSEG;
        int cn = (lane < NSEG) ? cnt[r0 + lane] : 0;
        if (cn > DW) cn = DW;
        float accs[NSEG];
#pragma unroll
        for (int sg = 0; sg < NSEG; ++sg) {
            const int n = __shfl_sync(0xffffffffu, cn, sg);
            const u64* e = ell + (size_t)(r0 + sg) * DW;
            float acc = 0.f;
            int j = 0;
            for (; j + 4 <= n; j += 4) {
                const u64 e0 = e[j], e1 = e[j + 1], e2 = e[j + 2], e3 = e[j + 3];
                acc += __uint_as_float((unsigned)(e0 >> 32)) * *(const float*)(sb + (unsigned)e0);
                acc += __uint_as_float((unsigned)(e1 >> 32)) * *(const float*)(sb + (unsigned)e1);
                acc += __uint_as_float((unsigned)(e2 >> 32)) * *(const float*)(sb + (unsigned)e2);
                acc += __uint_as_float((unsigned)(e3 >> 32)) * *(const float*)(sb + (unsigned)e3);
            }
            for (; j < n; ++j) {
                const u64 e0 = e[j];
                acc += __uint_as_float((unsigned)(e0 >> 32)) * *(const float*)(sb + (unsigned)e0);
            }
            accs[sg] = acc;
        }
        // first-occurrence abs-argmax (strict >) + sigmoid
        float best = accs[0];
        float ba = fabsf(best);
#pragma unroll
        for (int sg = 1; sg < NSEG; ++sg) {
            const float v = accs[sg];
            const float a = fabsf(v);
            if (a > ba) { ba = a; best = v; }
        }
        gT[(size_t)u * 256 + b0 + lane] = 1.0f / (1.0f + __expf(-best));
    }
}

// =====================================================================
// FF spMM with FUSED GATE (the one new delta vs R6):
// yT[r][b] = (bias[r] + sum w*xT[c][b]) * gT[r][b]
// One block per output row (2048 blocks); entries staged in smem;
// unroll 8 for L2 MLP. gT read and yT write are both coalesced here.
// =====================================================================
__global__ __launch_bounds__(256)
void fspmm(const float* __restrict__ xT, const u64* __restrict__ ell,
           const int* __restrict__ cnt, const float* __restrict__ bias,
           const float* __restrict__ gT, float* __restrict__ yT) {
    __shared__ u64 fe[FW];
    const int r = blockIdx.x;
    const int tid = threadIdx.x;
    const int n = cnt[r];
    for (int j = tid; j < n; j += 256) fe[j] = ell[(size_t)r * FW + j];
    __syncthreads();
    const char* xb = (const char*)xT + tid * 4;
    float acc = 0.f;
    int j = 0;
    for (; j + 8 <= n; j += 8) {
        float p = 0.f;
#pragma unroll
        for (int q = 0; q < 8; ++q) {
            const u64 e = fe[j + q];
            p += __uint_as_float((unsigned)(e >> 32)) * *(const float*)(xb + (unsigned)e);
        }
        acc += p;
    }
    for (; j < n; ++j) {
        const u64 e = fe[j];
        acc += __uint_as_float((unsigned)(e >> 32)) * *(const float*)(xb + (unsigned)e);
    }
    yT[(size_t)r * 256 + tid] = (acc + bias[r]) * gT[(size_t)r * 256 + tid];
}

// =====================================================================
// k-winners: exact top-KWIN per sample; gate already applied upstream,
// so only ONE strided stream is read. 4-pass radix select with
// single-warp shfl suffix scan. Values reconstructed from keys.
// mode 0 -> transposed hT[i][b]; mode 1 -> row-major h2[b][i].
// =====================================================================
__global__ __launch_bounds__(256)
void kwinners_k(const float* __restrict__ yT, float* __restrict__ outT,
                float* __restrict__ outN, int mode) {
    __shared__ unsigned keys[HID];
    __shared__ int hist[256];
    __shared__ int s_digit;
    __shared__ int s_need;
    const int b = blockIdx.x, tid = threadIdx.x;
    for (int i = tid; i < HID; i += 256) {
        unsigned u = __float_as_uint(yT[(size_t)i * 256 + b]);
        u = (u & 0x80000000u) ? ~u : (u | 0x80000000u);  // monotonic ascending
        keys[i] = u;
    }
    if (tid == 0) s_need = KWIN;
    __syncthreads();

    unsigned prefix = 0, pmask = 0;
    for (int pass = 0; pass < 4; ++pass) {
        const int shift = 24 - 8 * pass;
        hist[tid] = 0;
        __syncthreads();
        for (int i = tid; i < HID; i += 256) {
            const unsigned u = keys[i];
            if ((u & pmask) == prefix) atomicAdd(&hist[(u >> shift) & 255], 1);
        }
        __syncthreads();
        if (tid < 32) {
            const int need = s_need;
            const int base = tid * 8;
            int gs = 0;
#pragma unroll
            for (int k = 0; k < 8; ++k) gs += hist[base + k];
            int S = gs;  // inclusive suffix sum across lanes
#pragma unroll
            for (int o = 1; o < 32; o <<= 1) {
                const int t = __shfl_down_sync(0xffffffffu, S, o);
                if (tid + o < 32) S += t;
            }
            int Snext = __shfl_down_sync(0xffffffffu, S, 1);
            if (tid == 31) Snext = 0;
            if (S >= need && Snext < need) {  // unique crossing lane
                int c = Snext;
#pragma unroll
                for (int k = 7; k >= 0; --k) {
                    const int hb = hist[base + k];
                    if (c + hb >= need) { s_digit = base + k; s_need = need - c; break; }
                    c += hb;
                }
            }
        }
        __syncthreads();
        prefix |= ((unsigned)s_digit) << shift;
        pmask |= 0xFFu << shift;
    }
    const unsigned thr = prefix;  // key of the KWIN-th largest
    for (int i = tid; i < HID; i += 256) {
        const unsigned u = keys[i];
        float val = 0.f;
        if (u >= thr) {
            const unsigned ob = (u & 0x80000000u) ? (u & 0x7FFFFFFFu) : ~u;
            val = __uint_as_float(ob);
        }
        if (mode == 0) outT[(size_t)i * 256 + b] = val;
        else           outN[(size_t)b * HID + i] = val;
    }
}

// =====================================================================
// EiDense head: out[b,o] = h.Wex[o] - (h.Wix)*Wei[o] + b_out[o]
// =====================================================================
__global__ __launch_bounds__(256)
void head_kernel(const float* __restrict__ h, const float* __restrict__ Wex,
                 const float* __restrict__ Wix, const float* __restrict__ Wei,
                 const float* __restrict__ bo, float* __restrict__ out) {
    __shared__ alignas(16) float sh[4][HID];
    __shared__ float st[4];
    const int b0 = blockIdx.x * 4;
    const int tid = threadIdx.x;
    for (int i = tid; i < 4 * HID; i += 256)
        (&sh[0][0])[i] = h[(size_t)b0 * HID + i];
    __syncthreads();
    const int wid = tid >> 5;
    const int lane = tid & 31;
    if (wid < 4) {
        float p = 0.f;
        for (int u = lane; u < HID; u += 32) p += sh[wid][u] * Wix[u];
#pragma unroll
        for (int o = 16; o; o >>= 1) p += __shfl_xor_sync(0xffffffffu, p, o);
        if (lane == 0) st[wid] = p;
    }
    __syncthreads();
    for (int o = wid; o < OUTD; o += 8) {
        float a0 = 0.f, a1 = 0.f, a2 = 0.f, a3 = 0.f;
        const float* wrow = Wex + (size_t)o * HID;
        for (int u = lane; u < HID; u += 32) {
            const float w = wrow[u];
            a0 += sh[0][u] * w;
            a1 += sh[1][u] * w;
            a2 += sh[2][u] * w;
            a3 += sh[3][u] * w;
        }
#pragma unroll
        for (int sft = 16; sft; sft >>= 1) {
            a0 += __shfl_xor_sync(0xffffffffu, a0, sft);
            a1 += __shfl_xor_sync(0xffffffffu, a1, sft);
            a2 += __shfl_xor_sync(0xffffffffu, a2, sft);
            a3 += __shfl_xor_sync(0xffffffffu, a3, sft);
        }
        if (lane == 0) {
            const float we = Wei[o];
            const float bb = bo[o];
            out[(size_t)(b0 + 0) * OUTD + o] = a0 - st[0] * we + bb;
            out[(size_t)(b0 + 1) * OUTD + o] = a1 - st[1] * we + bb;
            out[(size_t)(b0 + 2) * OUTD + o] = a2 - st[2] * we + bb;
            out[(size_t)(b0 + 3) * OUTD + o] = a3 - st[3] * we + bb;
        }
    }
}

// =====================================================================
// launch
// =====================================================================
extern "C" void kernel_launch(void* const* d_in, const int* in_sizes, int n_in,
                              void* d_out, int out_size) {
    const float* x      = (const float*)d_in[0];
    const float* ctx    = (const float*)d_in[1];
    const float* W1     = (const float*)d_in[2];
    const float* b1     = (const float*)d_in[3];
    const float* segW1  = (const float*)d_in[4];
    const float* maskW1 = (const float*)d_in[5];
    const float* maskS1 = (const float*)d_in[6];
    const float* W2     = (const float*)d_in[7];
    const float* b2     = (const float*)d_in[8];
    const float* segW2  = (const float*)d_in[9];
    const float* maskW2 = (const float*)d_in[10];
    const float* maskS2 = (const float*)d_in[11];
    const float* Wex    = (const float*)d_in[12];
    const float* Wix    = (const float*)d_in[13];
    const float* Wei    = (const float*)d_in[14];
    const float* bo     = (const float*)d_in[15];
    float* out = (float*)d_out;

    float *ctxT, *xT, *hT, *yT, *gT1, *gT2, *h2;
    u64 *ellF1, *ellF2;
    int *cntF1, *cntF2;
    cudaGetSymbolAddress((void**)&ctxT,  g_ctxT);
    cudaGetSymbolAddress((void**)&xT,    g_xT);
    cudaGetSymbolAddress((void**)&hT,    g_hT);
    cudaGetSymbolAddress((void**)&yT,    g_yT);
    cudaGetSymbolAddress((void**)&gT1,   g_gT1);
    cudaGetSymbolAddress((void**)&gT2,   g_gT2);
    cudaGetSymbolAddress((void**)&h2,    g_h2);
    cudaGetSymbolAddress((void**)&ellF1, g_ellF1);
    cudaGetSymbolAddress((void**)&ellF2, g_ellF2);
    cudaGetSymbolAddress((void**)&cntF1, g_cntF1);
    cudaGetSymbolAddress((void**)&cntF2, g_cntF2);

    const int dsmem = DCTX * 32 * 4;  // 128 KB
    cudaFuncSetAttribute(dspmm_gate2, cudaFuncAttributeMaxDynamicSharedMemorySize, dsmem);

    // K1: all builds + transposes fused
    prep_k<<<6400, 256>>>(segW1, maskS1, segW2, maskS2,
                          W1, maskW1, W2, maskW2, ctx, x);
    // K2: both layers' dendrite gates (needs ctxT + ellD)
    dspmm_gate2<<<256, 1024, dsmem>>>(ctxT);
    // layer 1 FF + gate (gate read coalesced here)
    fspmm<<<HID, 256>>>(xT, ellF1, cntF1, b1, gT1, yT);
    // layer 1 k-winners -> hT (transposed, for fspmm2)
    kwinners_k<<<BDIM, 256>>>(yT, hT, h2, 0);
    // layer 2 FF + gate
    fspmm<<<HID, 256>>>(hT, ellF2, cntF2, b2, gT2, yT);
    // layer 2 k-winners -> h2 row-major
    kwinners_k<<<BDIM, 256>>>(yT, hT, h2, 1);
    // EiDense head
    head_kernel<<<BDIM / 4, 256>>>(h2, Wex, Wix, Wei, bo, out);
}